// round 3
// baseline (speedup 1.0000x reference)
#include <cuda_runtime.h>
#include <cstdint>

#define LROW 4096
#define THREADS 256
#define VPT (LROW / 4 / THREADS)   // int4 mask quads per thread = 4

// ---------------------------------------------------------------------------
// Fused pass-through + mask-suffix-fill.
// Inputs:  x [B,4096] f32, mask [B,4096] int32 (bool as 0/1 words)
// Output:  d_out = [x (n floats) | new_mask (n floats, 0.0/1.0)]
// cutoff = min(ceil(float(valid_len) * 0.7f), L-1), exactly mirroring the
// reference's float32 math. new_mask[j] = mask[j] | (j >= cutoff).
// One CTA per row; everything 16B vectorized and coalesced.
// ---------------------------------------------------------------------------
__global__ void __launch_bounds__(THREADS)
subset_kernel(const float4* __restrict__ x,
              const int4* __restrict__ mask,
              float4* __restrict__ out_x,
              float4* __restrict__ out_m) {
    const int row = blockIdx.x;
    const int tid = threadIdx.x;
    const size_t rbase = (size_t)row * (LROW / 4);   // in 16B quads

    // load mask row (int32 0/1 per element)
    int4 mv[VPT];
#pragma unroll
    for (int i = 0; i < VPT; i++)
        mv[i] = mask[rbase + tid + i * THREADS];

    // count True entries
    int s = 0;
#pragma unroll
    for (int i = 0; i < VPT; i++)
        s += mv[i].x + mv[i].y + mv[i].z + mv[i].w;

    // block reduction (8 warps)
    __shared__ int warp_sums[THREADS / 32];
    for (int o = 16; o; o >>= 1) s += __shfl_xor_sync(0xffffffffu, s, o);
    const int lane = threadIdx.x & 31;
    const int wid  = threadIdx.x >> 5;
    if (lane == 0) warp_sums[wid] = s;
    __syncthreads();
    int total = 0;
#pragma unroll
    for (int i = 0; i < THREADS / 32; i++) total += warp_sums[i];

    const int length = LROW - total;                     // valid length
    int cutoff = (int)ceilf((float)length * 0.7f);       // f32 math like ref
    if (cutoff > LROW - 1) cutoff = LROW - 1;

    // write new mask as floats 0.0/1.0
#pragma unroll
    for (int i = 0; i < VPT; i++) {
        const int idx = tid + i * THREADS;
        const int j = idx * 4;
        const int4 v = mv[i];
        float4 o;
        o.x = (v.x || (j + 0 >= cutoff)) ? 1.0f : 0.0f;
        o.y = (v.y || (j + 1 >= cutoff)) ? 1.0f : 0.0f;
        o.z = (v.z || (j + 2 >= cutoff)) ? 1.0f : 0.0f;
        o.w = (v.w || (j + 3 >= cutoff)) ? 1.0f : 0.0f;
        out_m[rbase + idx] = o;
    }

    // pass-through copy of x row
#pragma unroll
    for (int i = 0; i < VPT; i++) {
        const int idx = tid + i * THREADS;
        out_x[rbase + idx] = x[rbase + idx];
    }
}

extern "C" void kernel_launch(void* const* d_in, const int* in_sizes, int n_in,
                              void* d_out, int out_size) {
    const float* x    = (const float*)d_in[0];
    const int*   mask = (const int*)d_in[1];        // bool transported as int32
    const long long n = (long long)in_sizes[0];     // B*L elements of x
    const int B = (int)(n / LROW);

    float* out_x = (float*)d_out;
    float* out_m = out_x + n;                        // [x | new_mask]
    subset_kernel<<<B, THREADS>>>((const float4*)x, (const int4*)mask,
                                  (float4*)out_x, (float4*)out_m);
}

// round 4
// speedup vs baseline: 1.0047x; 1.0047x over previous
#include <cuda_runtime.h>
#include <cstdint>

#define LROW 4096
#define THREADS 256
#define VPT (LROW / 4 / THREADS)   // 16B quads per thread per stream = 4

// ---------------------------------------------------------------------------
// Fused pass-through + mask-suffix-fill. HBM-bound streaming kernel.
// Inputs:  x [B,4096] f32, mask [B,4096] int32 (bool as 0/1 words)
// Output:  d_out = [x (n floats) | new_mask (n floats, 0.0/1.0)]
// cutoff = min(ceil(float(valid_len) * 0.7f), L-1)  (f32 math, like reference)
//
// Optimization vs R3: all 8 LDG.128 (4 mask + 4 x) issued up front so the
// block reduction + __syncthreads latency is hidden under the x-load
// scoreboard; streaming cache hints (.cs) on every access since nothing is
// reused.
// ---------------------------------------------------------------------------
__global__ void __launch_bounds__(THREADS)
subset_kernel(const float4* __restrict__ x,
              const int4* __restrict__ mask,
              float4* __restrict__ out_x,
              float4* __restrict__ out_m) {
    const int row = blockIdx.x;
    const int tid = threadIdx.x;
    const size_t rbase = (size_t)row * (LROW / 4);   // in 16B quads

    // ---- front-batch ALL loads (MLP_p1 = 8) ----
    int4 mv[VPT];
#pragma unroll
    for (int i = 0; i < VPT; i++)
        mv[i] = __ldcs(&mask[rbase + tid + i * THREADS]);

    float4 xv[VPT];
#pragma unroll
    for (int i = 0; i < VPT; i++)
        xv[i] = __ldcs(&x[rbase + tid + i * THREADS]);

    // ---- count True entries (mask words are 0/1) ----
    int s = 0;
#pragma unroll
    for (int i = 0; i < VPT; i++)
        s += mv[i].x + mv[i].y + mv[i].z + mv[i].w;

    // block reduction (8 warps) — latency overlapped with in-flight x loads
    __shared__ int warp_sums[THREADS / 32];
    for (int o = 16; o; o >>= 1) s += __shfl_xor_sync(0xffffffffu, s, o);
    const int lane = threadIdx.x & 31;
    const int wid  = threadIdx.x >> 5;
    if (lane == 0) warp_sums[wid] = s;
    __syncthreads();
    int total = 0;
#pragma unroll
    for (int i = 0; i < THREADS / 32; i++) total += warp_sums[i];

    const int length = LROW - total;                  // valid length
    int cutoff = (int)ceilf((float)length * 0.7f);    // f32 math like ref
    if (cutoff > LROW - 1) cutoff = LROW - 1;

    // ---- streaming stores ----
#pragma unroll
    for (int i = 0; i < VPT; i++) {
        const int idx = tid + i * THREADS;
        __stcs(&out_x[rbase + idx], xv[i]);
    }

#pragma unroll
    for (int i = 0; i < VPT; i++) {
        const int idx = tid + i * THREADS;
        const int j = idx * 4;
        const int4 v = mv[i];
        float4 o;
        o.x = (v.x || (j + 0 >= cutoff)) ? 1.0f : 0.0f;
        o.y = (v.y || (j + 1 >= cutoff)) ? 1.0f : 0.0f;
        o.z = (v.z || (j + 2 >= cutoff)) ? 1.0f : 0.0f;
        o.w = (v.w || (j + 3 >= cutoff)) ? 1.0f : 0.0f;
        __stcs(&out_m[rbase + idx], o);
    }
}

extern "C" void kernel_launch(void* const* d_in, const int* in_sizes, int n_in,
                              void* d_out, int out_size) {
    const float* x    = (const float*)d_in[0];
    const int*   mask = (const int*)d_in[1];        // bool transported as int32
    const long long n = (long long)in_sizes[0];     // B*L elements of x
    const int B = (int)(n / LROW);

    float* out_x = (float*)d_out;
    float* out_m = out_x + n;                        // [x | new_mask]
    subset_kernel<<<B, THREADS>>>((const float4*)x, (const int4*)mask,
                                  (float4*)out_x, (float4*)out_m);
}